// round 8
// baseline (speedup 1.0000x reference)
#include <cuda_runtime.h>
#include <cuda_bf16.h>
#include <cstdint>

#define N_NODES 100000
#define N_EDGES 500000
#define FIN 128
#define D1 256
#define NHEADS 4
#define HID 64
#define OUTC 32
#define NEG_SLOPE 0.2f

#define SCAN_B 512
#define SCAN_NB ((N_NODES + SCAN_B - 1) / SCAN_B)   // 196

typedef unsigned long long ull;

// ---------------- scratch (device globals; no allocation) ----------------
__device__ float g_xl1[N_NODES * D1];
__device__ float g_xr1[N_NODES * D1];
__device__ float g_h1[N_NODES * D1];
__device__ float g_xl2[N_NODES * OUTC];
__device__ float g_xr2[N_NODES * OUTC];
__device__ int   g_deg[N_NODES];
__device__ int   g_off[N_NODES + 1];
__device__ int   g_cursor[N_NODES];
__device__ int   g_bsum[SCAN_NB + 1];
__device__ int   g_ssrc[N_EDGES];
__device__ float g_sea[N_EDGES];
// pre-split weights, padded layouts for conflict-free SMEM fragment loads:
// layer1: 4 ntiles x [n=128][k=132 pad]   layer2: [n=64][k=264 pad]
__device__ __align__(16) __nv_bfloat16 g_W1hi[4 * 128 * 132];
__device__ __align__(16) __nv_bfloat16 g_W1lo[4 * 128 * 132];
__device__ __align__(16) __nv_bfloat16 g_W2hi[64 * 264];
__device__ __align__(16) __nv_bfloat16 g_W2lo[64 * 264];

// ---------------- mma.sync helper (baseline PTX, works on family target) ----
__device__ __forceinline__ void mma16816(float* c, const unsigned* a, const unsigned* b) {
    asm volatile(
        "mma.sync.aligned.m16n8k16.row.col.f32.bf16.bf16.f32 "
        "{%0,%1,%2,%3}, {%4,%5,%6,%7}, {%8,%9}, {%0,%1,%2,%3};"
        : "+f"(c[0]), "+f"(c[1]), "+f"(c[2]), "+f"(c[3])
        : "r"(a[0]), "r"(a[1]), "r"(a[2]), "r"(a[3]), "r"(b[0]), "r"(b[1]));
}

// ---------------- CSR build ----------------
__global__ void k_zero_deg() {
    int i = blockIdx.x * blockDim.x + threadIdx.x;
    if (i < N_NODES) g_deg[i] = 0;
}

__global__ void k_count(const int* __restrict__ ei) {
    int i = blockIdx.x * blockDim.x + threadIdx.x;
    if (i < N_EDGES) atomicAdd(&g_deg[ei[N_EDGES + i]], 1);
}

__global__ void k_scan1() {
    __shared__ int sh[SCAN_B];
    int t = threadIdx.x;
    int i = blockIdx.x * SCAN_B + t;
    int v = (i < N_NODES) ? g_deg[i] : 0;
    sh[t] = v;
    __syncthreads();
    for (int off = 1; off < SCAN_B; off <<= 1) {
        int add = (t >= off) ? sh[t - off] : 0;
        __syncthreads();
        sh[t] += add;
        __syncthreads();
    }
    if (i < N_NODES) g_off[i] = sh[t];
    if (t == SCAN_B - 1) g_bsum[blockIdx.x] = sh[t];
}

__global__ void k_scan2() {
    __shared__ int sh[256];
    int t = threadIdx.x;
    int v = (t < SCAN_NB) ? g_bsum[t] : 0;
    sh[t] = v;
    __syncthreads();
    for (int off = 1; off < 256; off <<= 1) {
        int add = (t >= off) ? sh[t - off] : 0;
        __syncthreads();
        sh[t] += add;
        __syncthreads();
    }
    if (t < SCAN_NB) g_bsum[t] = sh[t] - v;
}

__global__ void k_scan3() {
    int i = blockIdx.x * blockDim.x + threadIdx.x;
    if (i < N_NODES) {
        int excl = g_off[i] - g_deg[i] + g_bsum[i / SCAN_B];
        g_off[i] = excl;
        g_cursor[i] = excl;
    }
    if (i == 0) g_off[N_NODES] = N_EDGES;
}

__global__ void k_scatter(const int* __restrict__ ei, const float* __restrict__ ea) {
    int i = blockIdx.x * blockDim.x + threadIdx.x;
    if (i >= N_EDGES) return;
    int d = ei[N_EDGES + i];
    int pos = atomicAdd(&g_cursor[d], 1);
    g_ssrc[pos] = ei[i];
    g_sea[pos] = ea[i];
}

// ---------------- weight prep: split to bf16 hi/lo, padded [n][k] ----------
__global__ void k_prepW1(const float* __restrict__ Wl1, const float* __restrict__ Wr1) {
    int i = blockIdx.x * blockDim.x + threadIdx.x;
    if (i >= 4 * 128 * 128) return;
    int nt = i >> 14;
    int n = (i >> 7) & 127;
    int k = i & 127;
    int j = nt * 128 + n;   // global output col (0..511)
    float v = (j < D1) ? Wl1[k * D1 + j] : Wr1[k * D1 + (j - D1)];
    __nv_bfloat16 hi = __float2bfloat16(v);
    __nv_bfloat16 lo = __float2bfloat16(v - __bfloat162float(hi));
    int idx = nt * 128 * 132 + n * 132 + k;
    g_W1hi[idx] = hi;
    g_W1lo[idx] = lo;
}

__global__ void k_prepW2(const float* __restrict__ Wl2, const float* __restrict__ Wr2) {
    int i = blockIdx.x * blockDim.x + threadIdx.x;
    if (i >= 64 * 256) return;
    int n = i >> 8;
    int k = i & 255;
    float v = (n < OUTC) ? Wl2[k * OUTC + n] : Wr2[k * OUTC + (n - OUTC)];
    __nv_bfloat16 hi = __float2bfloat16(v);
    __nv_bfloat16 lo = __float2bfloat16(v - __bfloat162float(hi));
    g_W2hi[n * 264 + k] = hi;
    g_W2lo[n * 264 + k] = lo;
}

// ---------------- split-bf16 warp-MMA GEMM ----------------
// D = A@[Bl|Br] + bias via Ahi*Bhi + Ahi*Blo + Alo*Bhi (fp32 accum).
// MODE 0: A=x (K=128), 4 ntiles of 128 cols -> g_xl1|g_xr1
// MODE 1: A=g_h1 (K=256, 2 chunks), 1 ntile of 64 cols -> g_xl2|g_xr2
// 256 threads, 8 warps in 4x2; warp tile 32 x (64|32).
#define SMEM_GEMM (4 * 16896 * 2)   // 4 buffers of 128*132 bf16 = 135168 B

template<int MODE>
__global__ __launch_bounds__(256, 1) void gemm_mma(const float* __restrict__ Aext,
                                                   const float* __restrict__ biasL,
                                                   const float* __restrict__ biasR) {
    constexpr int NFRAG = (MODE == 0) ? 8 : 4;
    constexpr int BSTR  = (MODE == 0) ? 132 : 264;
    constexpr int NT    = (MODE == 0) ? 4 : 1;
    constexpr int KCH   = (MODE == 0) ? 1 : 2;
    constexpr int KTOT  = (MODE == 0) ? FIN : D1;
    constexpr int SPLIT = (MODE == 0) ? D1 : OUTC;

    extern __shared__ __nv_bfloat16 sm[];
    __nv_bfloat16* AHI = sm;
    __nv_bfloat16* ALO = AHI + 16896;
    __nv_bfloat16* BHI = ALO + 16896;
    __nv_bfloat16* BLO = BHI + 16896;

    const int tid = threadIdx.x;
    const int wid = tid >> 5, lane = tid & 31;
    const int g = lane >> 2, t = lane & 3;
    const int wr = wid >> 1, wc = wid & 1;
    const int row0 = blockIdx.x * 128;
    const int wrow = wr * 32;
    const int wcol = wc * ((MODE == 0) ? 64 : 32);

    const float* A = (MODE == 0) ? Aext : g_h1;
    float* D0 = (MODE == 0) ? g_xl1 : g_xl2;
    float* D1p = (MODE == 0) ? g_xr1 : g_xr2;
    const __nv_bfloat16* GBH = (MODE == 0) ? g_W1hi : g_W2hi;
    const __nv_bfloat16* GBL = (MODE == 0) ? g_W1lo : g_W2lo;

    float acc[2][NFRAG][4];

    // ---- MODE1: load B (full K) once ----
    if (MODE == 1) {
        const int4* sh = (const int4*)GBH;
        const int4* sl = (const int4*)GBL;
        int4* dh = (int4*)BHI;
        int4* dl = (int4*)BLO;
        for (int i = tid; i < 2112; i += 256) { dh[i] = sh[i]; dl[i] = sl[i]; }
#pragma unroll
        for (int mf = 0; mf < 2; mf++)
#pragma unroll
            for (int nf = 0; nf < NFRAG; nf++)
#pragma unroll
                for (int q = 0; q < 4; q++) acc[mf][nf][q] = 0.f;
    }

    for (int kc = 0; kc < KCH; kc++) {
        // ---- fill A chunk: 128 rows x 128 k, fp32 -> bf16 hi/lo ----
        for (int idx = tid; idx < 128 * 32; idx += 256) {
            int row = idx >> 5;
            int kq = (idx & 31) << 2;
            int gr = row0 + row;
            float4 v = {0.f, 0.f, 0.f, 0.f};
            if (gr < N_NODES)
                v = *(const float4*)(A + (long)gr * KTOT + kc * 128 + kq);
            __nv_bfloat16 h0 = __float2bfloat16(v.x);
            __nv_bfloat16 h1 = __float2bfloat16(v.y);
            __nv_bfloat16 h2 = __float2bfloat16(v.z);
            __nv_bfloat16 h3 = __float2bfloat16(v.w);
            __nv_bfloat16 l0 = __float2bfloat16(v.x - __bfloat162float(h0));
            __nv_bfloat16 l1 = __float2bfloat16(v.y - __bfloat162float(h1));
            __nv_bfloat16 l2 = __float2bfloat16(v.z - __bfloat162float(h2));
            __nv_bfloat16 l3 = __float2bfloat16(v.w - __bfloat162float(h3));
            __nv_bfloat162* ph = (__nv_bfloat162*)&AHI[row * 132 + kq];
            __nv_bfloat162* pl = (__nv_bfloat162*)&ALO[row * 132 + kq];
            ph[0] = __nv_bfloat162(h0, h1);
            ph[1] = __nv_bfloat162(h2, h3);
            pl[0] = __nv_bfloat162(l0, l1);
            pl[1] = __nv_bfloat162(l2, l3);
        }

        for (int nt = 0; nt < NT; nt++) {
            if (MODE == 0) {
                // load B ntile (pre-padded, linear copy)
                const int4* sh = (const int4*)(GBH + nt * 16896);
                const int4* sl = (const int4*)(GBL + nt * 16896);
                int4* dh = (int4*)BHI;
                int4* dl = (int4*)BLO;
                for (int i = tid; i < 2112; i += 256) { dh[i] = sh[i]; dl[i] = sl[i]; }
            }
            __syncthreads();

            if (MODE == 0) {
#pragma unroll
                for (int mf = 0; mf < 2; mf++)
#pragma unroll
                    for (int nf = 0; nf < NFRAG; nf++)
#pragma unroll
                        for (int q = 0; q < 4; q++) acc[mf][nf][q] = 0.f;
            }

            const int kbase = (MODE == 1) ? kc * 128 : 0;
#pragma unroll
            for (int kk = 0; kk < 128; kk += 16) {
                unsigned ah[2][4], al[2][4];
#pragma unroll
                for (int mf = 0; mf < 2; mf++) {
                    const __nv_bfloat16* p = &AHI[(wrow + mf * 16 + g) * 132 + kk + 2 * t];
                    ah[mf][0] = *(const unsigned*)p;
                    ah[mf][1] = *(const unsigned*)(p + 8 * 132);
                    ah[mf][2] = *(const unsigned*)(p + 8);
                    ah[mf][3] = *(const unsigned*)(p + 8 * 132 + 8);
                    const __nv_bfloat16* pl = &ALO[(wrow + mf * 16 + g) * 132 + kk + 2 * t];
                    al[mf][0] = *(const unsigned*)pl;
                    al[mf][1] = *(const unsigned*)(pl + 8 * 132);
                    al[mf][2] = *(const unsigned*)(pl + 8);
                    al[mf][3] = *(const unsigned*)(pl + 8 * 132 + 8);
                }
#pragma unroll
                for (int nf = 0; nf < NFRAG; nf++) {
                    int n = wcol + nf * 8 + g;
                    const __nv_bfloat16* qh = &BHI[n * BSTR + kbase + kk + 2 * t];
                    const __nv_bfloat16* ql = &BLO[n * BSTR + kbase + kk + 2 * t];
                    unsigned bh[2] = { *(const unsigned*)qh, *(const unsigned*)(qh + 8) };
                    unsigned bl[2] = { *(const unsigned*)ql, *(const unsigned*)(ql + 8) };
                    mma16816(acc[0][nf], ah[0], bh);
                    mma16816(acc[1][nf], ah[1], bh);
                    mma16816(acc[0][nf], ah[0], bl);
                    mma16816(acc[1][nf], ah[1], bl);
                    mma16816(acc[0][nf], al[0], bh);
                    mma16816(acc[1][nf], al[1], bh);
                }
            }

            if (MODE == 0) {
                // epilogue per ntile
                int colbase = nt * 128 + wcol;
#pragma unroll
                for (int nf = 0; nf < NFRAG; nf++) {
                    int col = colbase + nf * 8 + 2 * t;
                    float* dest = (col < SPLIT) ? D0 : D1p;
                    int c = (col < SPLIT) ? col : col - SPLIT;
                    const float* bias = (col < SPLIT) ? biasL : biasR;
                    float bx = bias[c], by = bias[c + 1];
#pragma unroll
                    for (int mf = 0; mf < 2; mf++) {
                        int r = row0 + wrow + mf * 16 + g;
                        if (r < N_NODES) {
                            float2 o = {acc[mf][nf][0] + bx, acc[mf][nf][1] + by};
                            *(float2*)(dest + (long)r * SPLIT + c) = o;
                        }
                        if (r + 8 < N_NODES) {
                            float2 o = {acc[mf][nf][2] + bx, acc[mf][nf][3] + by};
                            *(float2*)(dest + (long)(r + 8) * SPLIT + c) = o;
                        }
                    }
                }
            }
            __syncthreads();
        }
    }

    if (MODE == 1) {
        // epilogue once (after both K chunks)
#pragma unroll
        for (int nf = 0; nf < NFRAG; nf++) {
            int col = wcol + nf * 8 + 2 * t;
            float* dest = (col < SPLIT) ? D0 : D1p;
            int c = (col < SPLIT) ? col : col - SPLIT;
            const float* bias = (col < SPLIT) ? biasL : biasR;
            float bx = bias[c], by = bias[c + 1];
#pragma unroll
            for (int mf = 0; mf < 2; mf++) {
                int r = row0 + wrow + mf * 16 + g;
                if (r < N_NODES) {
                    float2 o = {acc[mf][nf][0] + bx, acc[mf][nf][1] + by};
                    *(float2*)(dest + (long)r * SPLIT + c) = o;
                }
                if (r + 8 < N_NODES) {
                    float2 o = {acc[mf][nf][2] + bx, acc[mf][nf][3] + by};
                    *(float2*)(dest + (long)(r + 8) * SPLIT + c) = o;
                }
            }
        }
    }
}

// ---------------- fused layer-1 node kernel (pipelined) ----------------
__global__ void k_node1(const float* __restrict__ We1,
                        const float* __restrict__ att1,
                        const float* __restrict__ b1) {
    int node = (blockIdx.x * blockDim.x + threadIdx.x) >> 5;
    if (node >= N_NODES) return;
    int lane = threadIdx.x & 31;
    int cb = lane * 8;

    const float4* Rp = (const float4*)(g_xr1 + (long)node * D1 + cb);
    float4 r0 = Rp[0], r1 = Rp[1];
    const float4* Wp = (const float4*)(We1 + cb);
    float4 w0 = Wp[0], w1 = Wp[1];
    const float4* Tp = (const float4*)(att1 + cb);
    float4 a0 = Tp[0], a1 = Tp[1];

    float M = -3.0e38f, D = 0.f;
    float4 v0 = {0.f, 0.f, 0.f, 0.f}, v1 = {0.f, 0.f, 0.f, 0.f};

    int beg = g_off[node], end = g_off[node + 1];

    float e_n = 0.f;
    float4 l0_n = {0,0,0,0}, l1_n = {0,0,0,0};
    if (beg < end) {
        int s = g_ssrc[beg];
        e_n = g_sea[beg];
        const float4* Lp = (const float4*)(g_xl1 + (long)s * D1 + cb);
        l0_n = Lp[0]; l1_n = Lp[1];
    }

    for (int k = beg; k < end; ) {
        float4 l0 = l0_n, l1 = l1_n;
        float eav = e_n;
        k++;
        if (k < end) {
            int s = g_ssrc[k];
            e_n = g_sea[k];
            const float4* Lp = (const float4*)(g_xl1 + (long)s * D1 + cb);
            l0_n = Lp[0]; l1_n = Lp[1];
        }

        float p = 0.f;
#define TERM(LV, RV, WV, AV) { float tv = (LV) + (RV) + eav * (WV); \
        tv = (tv > 0.f) ? tv : NEG_SLOPE * tv; p += (AV) * tv; }
        TERM(l0.x, r0.x, w0.x, a0.x); TERM(l0.y, r0.y, w0.y, a0.y);
        TERM(l0.z, r0.z, w0.z, a0.z); TERM(l0.w, r0.w, w0.w, a0.w);
        TERM(l1.x, r1.x, w1.x, a1.x); TERM(l1.y, r1.y, w1.y, a1.y);
        TERM(l1.z, r1.z, w1.z, a1.z); TERM(l1.w, r1.w, w1.w, a1.w);
#undef TERM
        p += __shfl_xor_sync(0xffffffffu, p, 4);
        p += __shfl_xor_sync(0xffffffffu, p, 2);
        p += __shfl_xor_sync(0xffffffffu, p, 1);

        float newM = fmaxf(M, p);
        float scale = __expf(M - newM);
        float wgt = __expf(p - newM);
        D = D * scale + wgt;
        v0.x = v0.x * scale + wgt * l0.x; v0.y = v0.y * scale + wgt * l0.y;
        v0.z = v0.z * scale + wgt * l0.z; v0.w = v0.w * scale + wgt * l0.w;
        v1.x = v1.x * scale + wgt * l1.x; v1.y = v1.y * scale + wgt * l1.y;
        v1.z = v1.z * scale + wgt * l1.z; v1.w = v1.w * scale + wgt * l1.w;
        M = newM;
    }

    float inv = 1.f / (D + 1e-16f);
    const float4* Bp = (const float4*)(b1 + cb);
    float4 bb0 = Bp[0], bb1 = Bp[1];
    float4 o0, o1;
    o0.x = fmaxf(v0.x * inv + bb0.x, 0.f); o0.y = fmaxf(v0.y * inv + bb0.y, 0.f);
    o0.z = fmaxf(v0.z * inv + bb0.z, 0.f); o0.w = fmaxf(v0.w * inv + bb0.w, 0.f);
    o1.x = fmaxf(v1.x * inv + bb1.x, 0.f); o1.y = fmaxf(v1.y * inv + bb1.y, 0.f);
    o1.z = fmaxf(v1.z * inv + bb1.z, 0.f); o1.w = fmaxf(v1.w * inv + bb1.w, 0.f);
    float4* Op = (float4*)(g_h1 + (long)node * D1 + cb);
    Op[0] = o0;
    Op[1] = o1;
}

// ---------------- fused layer-2 node kernel (pipelined) ----------------
__global__ void k_node2(const float* __restrict__ We2,
                        const float* __restrict__ att2,
                        const float* __restrict__ b2,
                        float* __restrict__ out) {
    int node = (blockIdx.x * blockDim.x + threadIdx.x) >> 5;
    if (node >= N_NODES) return;
    int lane = threadIdx.x & 31;

    float r = g_xr2[node * OUTC + lane];
    float w = We2[lane];
    float a = att2[lane];

    float M = -3.0e38f, D = 0.f, v = 0.f;

    int beg = g_off[node], end = g_off[node + 1];

    float e_n = 0.f, l_n = 0.f;
    if (beg < end) {
        int s = g_ssrc[beg];
        e_n = g_sea[beg];
        l_n = g_xl2[s * OUTC + lane];
    }

    for (int k = beg; k < end; ) {
        float l = l_n, eav = e_n;
        k++;
        if (k < end) {
            int s = g_ssrc[k];
            e_n = g_sea[k];
            l_n = g_xl2[s * OUTC + lane];
        }

        float t = l + r + eav * w;
        t = (t > 0.f) ? t : NEG_SLOPE * t;
        float p = a * t;
#pragma unroll
        for (int o = 16; o > 0; o >>= 1) p += __shfl_xor_sync(0xffffffffu, p, o);

        float newM = fmaxf(M, p);
        float scale = __expf(M - newM);
        float wgt = __expf(p - newM);
        D = D * scale + wgt;
        v = v * scale + wgt * l;
        M = newM;
    }

    out[node * OUTC + lane] = v / (D + 1e-16f) + b2[lane];
}

// ---------------- launch ----------------
extern "C" void kernel_launch(void* const* d_in, const int* in_sizes, int n_in,
                              void* d_out, int out_size) {
    const float* x    = (const float*)d_in[0];
    const int*   ei   = (const int*)d_in[1];
    const float* ea   = (const float*)d_in[2];
    const float* Wl1  = (const float*)d_in[3];
    const float* bl1  = (const float*)d_in[4];
    const float* Wr1  = (const float*)d_in[5];
    const float* br1  = (const float*)d_in[6];
    const float* We1  = (const float*)d_in[7];
    const float* att1 = (const float*)d_in[8];
    const float* b1   = (const float*)d_in[9];
    const float* Wl2  = (const float*)d_in[10];
    const float* bl2  = (const float*)d_in[11];
    const float* Wr2  = (const float*)d_in[12];
    const float* br2  = (const float*)d_in[13];
    const float* We2  = (const float*)d_in[14];
    const float* att2 = (const float*)d_in[15];
    const float* b2   = (const float*)d_in[16];
    float* out = (float*)d_out;

    cudaFuncSetAttribute(gemm_mma<0>, cudaFuncAttributeMaxDynamicSharedMemorySize, SMEM_GEMM);
    cudaFuncSetAttribute(gemm_mma<1>, cudaFuncAttributeMaxDynamicSharedMemorySize, SMEM_GEMM);

    // CSR build (counting sort by dst)
    k_zero_deg<<<(N_NODES + 255) / 256, 256>>>();
    k_count<<<(N_EDGES + 255) / 256, 256>>>(ei);
    k_scan1<<<SCAN_NB, SCAN_B>>>();
    k_scan2<<<1, 256>>>();
    k_scan3<<<(N_NODES + 255) / 256, 256>>>();
    k_scatter<<<(N_EDGES + 255) / 256, 256>>>(ei, ea);

    // weight prep (split + pad)
    k_prepW1<<<(4 * 128 * 128 + 255) / 256, 256>>>(Wl1, Wr1);
    k_prepW2<<<(64 * 256 + 255) / 256, 256>>>(Wl2, Wr2);

    int nblk = (N_NODES + 127) / 128;   // 782

    // layer-1 GEMM (tensor cores, split-bf16)
    gemm_mma<0><<<nblk, 256, SMEM_GEMM>>>(x, bl1, br1);

    // fused layer-1 attention + aggregation + relu
    int nwb = (N_NODES * 32 + 255) / 256;
    k_node1<<<nwb, 256>>>(We1, att1, b1);

    // layer-2 GEMM (tensor cores, split-bf16)
    gemm_mma<1><<<nblk, 256, SMEM_GEMM>>>(nullptr, bl2, br2);

    // fused layer-2 attention + aggregation + output
    k_node2<<<nwb, 256>>>(We2, att2, b2, out);
}

// round 9
// speedup vs baseline: 1.0972x; 1.0972x over previous
#include <cuda_runtime.h>
#include <cuda_bf16.h>

#define N_NODES 100000
#define N_EDGES 500000
#define FIN 128
#define D1 256
#define NHEADS 4
#define HID 64
#define OUTC 32
#define NEG_SLOPE 0.2f

#define SCAN_B 512
#define SCAN_NB ((N_NODES + SCAN_B - 1) / SCAN_B)   // 196

typedef unsigned long long ull;

// ---------------- scratch (device globals; no allocation) ----------------
__device__ float g_xl1[N_NODES * D1];
__device__ float g_xr1[N_NODES * D1];
__device__ float g_h1[N_NODES * D1];
__device__ float g_xl2[N_NODES * OUTC];
__device__ float g_xr2[N_NODES * OUTC];
__device__ int   g_deg[N_NODES];
__device__ int   g_off[N_NODES + 1];
__device__ int   g_cursor[N_NODES];
__device__ int   g_bsum[SCAN_NB + 1];
__device__ int   g_ssrc[N_EDGES];
__device__ float g_sea[N_EDGES];

// ---------------- f32x2 packed helpers ----------------
__device__ __forceinline__ void fma2(ull& d, ull a, ull b) {
    asm("fma.rn.f32x2 %0, %1, %2, %0;" : "+l"(d) : "l"(a), "l"(b));
}
__device__ __forceinline__ ull splat2(float x) {
    ull r; asm("mov.b64 %0, {%1, %2};" : "=l"(r) : "f"(x), "f"(x)); return r;
}
__device__ __forceinline__ float2 unpack2(ull p) {
    float2 r; asm("mov.b64 {%0, %1}, %2;" : "=f"(r.x), "=f"(r.y) : "l"(p)); return r;
}

// ---------------- CSR build ----------------
__global__ void k_zero_deg() {
    int i = blockIdx.x * blockDim.x + threadIdx.x;
    if (i < N_NODES) g_deg[i] = 0;
}

__global__ void k_count(const int* __restrict__ ei) {
    int i = blockIdx.x * blockDim.x + threadIdx.x;
    if (i < N_EDGES) atomicAdd(&g_deg[ei[N_EDGES + i]], 1);
}

__global__ void k_scan1() {
    __shared__ int sh[SCAN_B];
    int t = threadIdx.x;
    int i = blockIdx.x * SCAN_B + t;
    int v = (i < N_NODES) ? g_deg[i] : 0;
    sh[t] = v;
    __syncthreads();
    for (int off = 1; off < SCAN_B; off <<= 1) {
        int add = (t >= off) ? sh[t - off] : 0;
        __syncthreads();
        sh[t] += add;
        __syncthreads();
    }
    if (i < N_NODES) g_off[i] = sh[t];
    if (t == SCAN_B - 1) g_bsum[blockIdx.x] = sh[t];
}

__global__ void k_scan2() {
    __shared__ int sh[256];
    int t = threadIdx.x;
    int v = (t < SCAN_NB) ? g_bsum[t] : 0;
    sh[t] = v;
    __syncthreads();
    for (int off = 1; off < 256; off <<= 1) {
        int add = (t >= off) ? sh[t - off] : 0;
        __syncthreads();
        sh[t] += add;
        __syncthreads();
    }
    if (t < SCAN_NB) g_bsum[t] = sh[t] - v;
}

__global__ void k_scan3() {
    int i = blockIdx.x * blockDim.x + threadIdx.x;
    if (i < N_NODES) {
        int excl = g_off[i] - g_deg[i] + g_bsum[i / SCAN_B];
        g_off[i] = excl;
        g_cursor[i] = excl;
    }
    if (i == 0) g_off[N_NODES] = N_EDGES;
}

__global__ void k_scatter(const int* __restrict__ ei, const float* __restrict__ ea) {
    int i = blockIdx.x * blockDim.x + threadIdx.x;
    if (i >= N_EDGES) return;
    int d = ei[N_EDGES + i];
    int pos = atomicAdd(&g_cursor[d], 1);
    g_ssrc[pos] = ei[i];
    g_sea[pos] = ea[i];
}

// -------- dual-output SGEMM with packed f32x2 FMA: [C0|C1] = A@[Bl|Br] + bias --
// MODE 0: A=x (K=128), SPLIT=256, BN=128, microtile 8x8 -> g_xl1,g_xr1
// MODE 1: A=g_h1 (K=256), SPLIT=32, BN=64, microtile 8x4 -> g_xl2,g_xr2
template<int MODE>
__global__ __launch_bounds__(256) void sgemm_dual(const float* __restrict__ Aext,
                                                  const float* __restrict__ Bl,
                                                  const float* __restrict__ Br,
                                                  const float* __restrict__ bl,
                                                  const float* __restrict__ br) {
    constexpr int K     = (MODE == 0) ? FIN : D1;
    constexpr int SPLIT = (MODE == 0) ? D1  : OUTC;
    constexpr int BN    = (MODE == 0) ? 128 : 64;
    constexpr int TN    = BN / 16;
    constexpr int NP    = TN / 2;
    const float* A  = (MODE == 0) ? Aext : g_h1;
    float*       C0 = (MODE == 0) ? g_xl1 : g_xl2;
    float*       C1 = (MODE == 0) ? g_xr1 : g_xr2;

    __shared__ float As[16][132];
    __shared__ float Bs[16][BN + 4];

    const int tid = threadIdx.x;
    const int tx = tid & 15;
    const int ty = tid >> 4;
    const int row0 = blockIdx.y * 128;
    const int col0 = blockIdx.x * BN;

    ull acc2[8][NP];
#pragma unroll
    for (int i = 0; i < 8; i++)
#pragma unroll
        for (int j = 0; j < NP; j++) acc2[i][j] = 0ULL;

    for (int kk = 0; kk < K; kk += 16) {
#pragma unroll
        for (int i = 0; i < 2; i++) {
            int f = tid * 2 + i;
            int arow = f >> 2;
            int kq = (f & 3) * 4;
            int r = row0 + arow;
            float4 v = {0.f, 0.f, 0.f, 0.f};
            if (r < N_NODES)
                v = *(const float4*)(A + (long)r * K + kk + kq);
            As[kq + 0][arow] = v.x;
            As[kq + 1][arow] = v.y;
            As[kq + 2][arow] = v.z;
            As[kq + 3][arow] = v.w;
        }
        if (MODE == 0) {
#pragma unroll
            for (int i = 0; i < 2; i++) {
                int f = tid * 2 + i;
                int krow = f >> 5;
                int nq = (f & 31) * 4;
                int c4 = col0 + nq;
                const float* src = (c4 < SPLIT)
                    ? (Bl + (long)(kk + krow) * SPLIT + c4)
                    : (Br + (long)(kk + krow) * SPLIT + (c4 - SPLIT));
                *(float4*)&Bs[krow][nq] = *(const float4*)src;
            }
        } else {
            int krow = tid >> 4;
            int nq = (tid & 15) * 4;
            int c4 = col0 + nq;
            const float* src = (c4 < SPLIT)
                ? (Bl + (long)(kk + krow) * SPLIT + c4)
                : (Br + (long)(kk + krow) * SPLIT + (c4 - SPLIT));
            *(float4*)&Bs[krow][nq] = *(const float4*)src;
        }
        __syncthreads();

#pragma unroll
        for (int k = 0; k < 16; k++) {
            float4 a04 = *(const float4*)&As[k][ty * 8];
            float4 a48 = *(const float4*)&As[k][ty * 8 + 4];
            ull aa[8];
            aa[0] = splat2(a04.x); aa[1] = splat2(a04.y);
            aa[2] = splat2(a04.z); aa[3] = splat2(a04.w);
            aa[4] = splat2(a48.x); aa[5] = splat2(a48.y);
            aa[6] = splat2(a48.z); aa[7] = splat2(a48.w);
            const ull* Bp = (const ull*)&Bs[k][tx * TN];
            ull bb[NP];
#pragma unroll
            for (int j = 0; j < NP; j++) bb[j] = Bp[j];
#pragma unroll
            for (int i = 0; i < 8; i++)
#pragma unroll
                for (int j = 0; j < NP; j++) fma2(acc2[i][j], aa[i], bb[j]);
        }
        __syncthreads();
    }

    int c4 = col0 + tx * TN;
    const bool left = (c4 < SPLIT);
    const float* bp = left ? (bl + c4) : (br + (c4 - SPLIT));
    float* Cb = left ? (C0 + c4) : (C1 + (c4 - SPLIT));

    float bv[TN];
#pragma unroll
    for (int j = 0; j < TN; j++) bv[j] = bp[j];

#pragma unroll
    for (int i = 0; i < 8; i++) {
        int r = row0 + ty * 8 + i;
        if (r >= N_NODES) break;
        float o[TN];
#pragma unroll
        for (int j = 0; j < NP; j++) {
            float2 p = unpack2(acc2[i][j]);
            o[2 * j]     = p.x + bv[2 * j];
            o[2 * j + 1] = p.y + bv[2 * j + 1];
        }
#pragma unroll
        for (int j = 0; j < TN; j += 4)
            *(float4*)(Cb + (long)r * SPLIT + j) = *(float4*)&o[j];
    }
}

// ---------------- fused layer-1 node kernel (pipelined) ----------------
__global__ void k_node1(const float* __restrict__ We1,
                        const float* __restrict__ att1,
                        const float* __restrict__ b1) {
    int node = (blockIdx.x * blockDim.x + threadIdx.x) >> 5;
    if (node >= N_NODES) return;
    int lane = threadIdx.x & 31;
    int cb = lane * 8;

    const float4* Rp = (const float4*)(g_xr1 + (long)node * D1 + cb);
    float4 r0 = Rp[0], r1 = Rp[1];
    const float4* Wp = (const float4*)(We1 + cb);
    float4 w0 = Wp[0], w1 = Wp[1];
    const float4* Tp = (const float4*)(att1 + cb);
    float4 a0 = Tp[0], a1 = Tp[1];

    float M = -3.0e38f, D = 0.f;
    float4 v0 = {0.f, 0.f, 0.f, 0.f}, v1 = {0.f, 0.f, 0.f, 0.f};

    int beg = g_off[node], end = g_off[node + 1];

    float e_n = 0.f;
    float4 l0_n = {0,0,0,0}, l1_n = {0,0,0,0};
    if (beg < end) {
        int s = g_ssrc[beg];
        e_n = g_sea[beg];
        const float4* Lp = (const float4*)(g_xl1 + (long)s * D1 + cb);
        l0_n = Lp[0]; l1_n = Lp[1];
    }

    for (int k = beg; k < end; ) {
        float4 l0 = l0_n, l1 = l1_n;
        float eav = e_n;
        k++;
        if (k < end) {
            int s = g_ssrc[k];
            e_n = g_sea[k];
            const float4* Lp = (const float4*)(g_xl1 + (long)s * D1 + cb);
            l0_n = Lp[0]; l1_n = Lp[1];
        }

        float p = 0.f;
#define TERM(LV, RV, WV, AV) { float t = (LV) + (RV) + eav * (WV); \
        t = (t > 0.f) ? t : NEG_SLOPE * t; p += (AV) * t; }
        TERM(l0.x, r0.x, w0.x, a0.x); TERM(l0.y, r0.y, w0.y, a0.y);
        TERM(l0.z, r0.z, w0.z, a0.z); TERM(l0.w, r0.w, w0.w, a0.w);
        TERM(l1.x, r1.x, w1.x, a1.x); TERM(l1.y, r1.y, w1.y, a1.y);
        TERM(l1.z, r1.z, w1.z, a1.z); TERM(l1.w, r1.w, w1.w, a1.w);
#undef TERM
        p += __shfl_xor_sync(0xffffffffu, p, 4);
        p += __shfl_xor_sync(0xffffffffu, p, 2);
        p += __shfl_xor_sync(0xffffffffu, p, 1);

        float newM = fmaxf(M, p);
        float scale = __expf(M - newM);
        float wgt = __expf(p - newM);
        D = D * scale + wgt;
        v0.x = v0.x * scale + wgt * l0.x; v0.y = v0.y * scale + wgt * l0.y;
        v0.z = v0.z * scale + wgt * l0.z; v0.w = v0.w * scale + wgt * l0.w;
        v1.x = v1.x * scale + wgt * l1.x; v1.y = v1.y * scale + wgt * l1.y;
        v1.z = v1.z * scale + wgt * l1.z; v1.w = v1.w * scale + wgt * l1.w;
        M = newM;
    }

    float inv = 1.f / (D + 1e-16f);
    const float4* Bp = (const float4*)(b1 + cb);
    float4 bb0 = Bp[0], bb1 = Bp[1];
    float4 o0, o1;
    o0.x = fmaxf(v0.x * inv + bb0.x, 0.f); o0.y = fmaxf(v0.y * inv + bb0.y, 0.f);
    o0.z = fmaxf(v0.z * inv + bb0.z, 0.f); o0.w = fmaxf(v0.w * inv + bb0.w, 0.f);
    o1.x = fmaxf(v1.x * inv + bb1.x, 0.f); o1.y = fmaxf(v1.y * inv + bb1.y, 0.f);
    o1.z = fmaxf(v1.z * inv + bb1.z, 0.f); o1.w = fmaxf(v1.w * inv + bb1.w, 0.f);
    float4* Op = (float4*)(g_h1 + (long)node * D1 + cb);
    Op[0] = o0;
    Op[1] = o1;
}

// ---------------- fused layer-2 node kernel (pipelined) ----------------
__global__ void k_node2(const float* __restrict__ We2,
                        const float* __restrict__ att2,
                        const float* __restrict__ b2,
                        float* __restrict__ out) {
    int node = (blockIdx.x * blockDim.x + threadIdx.x) >> 5;
    if (node >= N_NODES) return;
    int lane = threadIdx.x & 31;

    float r = g_xr2[node * OUTC + lane];
    float w = We2[lane];
    float a = att2[lane];

    float M = -3.0e38f, D = 0.f, v = 0.f;

    int beg = g_off[node], end = g_off[node + 1];

    float e_n = 0.f, l_n = 0.f;
    if (beg < end) {
        int s = g_ssrc[beg];
        e_n = g_sea[beg];
        l_n = g_xl2[s * OUTC + lane];
    }

    for (int k = beg; k < end; ) {
        float l = l_n, eav = e_n;
        k++;
        if (k < end) {
            int s = g_ssrc[k];
            e_n = g_sea[k];
            l_n = g_xl2[s * OUTC + lane];
        }

        float t = l + r + eav * w;
        t = (t > 0.f) ? t : NEG_SLOPE * t;
        float p = a * t;
#pragma unroll
        for (int o = 16; o > 0; o >>= 1) p += __shfl_xor_sync(0xffffffffu, p, o);

        float newM = fmaxf(M, p);
        float scale = __expf(M - newM);
        float wgt = __expf(p - newM);
        D = D * scale + wgt;
        v = v * scale + wgt * l;
        M = newM;
    }

    out[node * OUTC + lane] = v / (D + 1e-16f) + b2[lane];
}

// ---------------- launch ----------------
extern "C" void kernel_launch(void* const* d_in, const int* in_sizes, int n_in,
                              void* d_out, int out_size) {
    const float* x    = (const float*)d_in[0];
    const int*   ei   = (const int*)d_in[1];
    const float* ea   = (const float*)d_in[2];
    const float* Wl1  = (const float*)d_in[3];
    const float* bl1  = (const float*)d_in[4];
    const float* Wr1  = (const float*)d_in[5];
    const float* br1  = (const float*)d_in[6];
    const float* We1  = (const float*)d_in[7];
    const float* att1 = (const float*)d_in[8];
    const float* b1   = (const float*)d_in[9];
    const float* Wl2  = (const float*)d_in[10];
    const float* bl2  = (const float*)d_in[11];
    const float* Wr2  = (const float*)d_in[12];
    const float* br2  = (const float*)d_in[13];
    const float* We2  = (const float*)d_in[14];
    const float* att2 = (const float*)d_in[15];
    const float* b2   = (const float*)d_in[16];
    float* out = (float*)d_out;

    // side stream + fork/join events, created once on the (uncaptured)
    // correctness call; reused in every captured/replayed launch.
    static cudaStream_t s2 = nullptr;
    static cudaEvent_t  evFork = nullptr, evJoin = nullptr;
    if (s2 == nullptr) {
        cudaStreamCreateWithFlags(&s2, cudaStreamNonBlocking);
        cudaEventCreateWithFlags(&evFork, cudaEventDisableTiming);
        cudaEventCreateWithFlags(&evJoin, cudaEventDisableTiming);
    }

    // fork: CSR build chain runs on s2, concurrent with layer-1 GEMM on 0
    cudaEventRecord(evFork, 0);
    cudaStreamWaitEvent(s2, evFork, 0);

    k_zero_deg<<<(N_NODES + 255) / 256, 256, 0, s2>>>();
    k_count<<<(N_EDGES + 255) / 256, 256, 0, s2>>>(ei);
    k_scan1<<<SCAN_NB, SCAN_B, 0, s2>>>();
    k_scan2<<<1, 256, 0, s2>>>();
    k_scan3<<<(N_NODES + 255) / 256, 256, 0, s2>>>();
    k_scatter<<<(N_EDGES + 255) / 256, 256, 0, s2>>>(ei, ea);

    // layer-1 fused GEMM on the main stream (independent of CSR)
    dim3 g1((2 * D1) / 128, (N_NODES + 127) / 128);
    sgemm_dual<0><<<g1, 256>>>(x, Wl1, Wr1, bl1, br1);

    // join: node kernels need both CSR and GEMM1
    cudaEventRecord(evJoin, s2);
    cudaStreamWaitEvent(0, evJoin, 0);

    // fused layer-1 attention + aggregation + relu
    int nwb = (N_NODES * 32 + 255) / 256;
    k_node1<<<nwb, 256>>>(We1, att1, b1);

    // layer-2 fused GEMM (f32x2)
    dim3 g2(1, (N_NODES + 127) / 128);
    sgemm_dual<1><<<g2, 256>>>(nullptr, Wl2, Wr2, bl2, br2);

    // fused layer-2 attention + aggregation + output
    k_node2<<<nwb, 256>>>(We2, att2, b2, out);
}